// round 1
// baseline (speedup 1.0000x reference)
#include <cuda_runtime.h>
#include <math.h>

#define Bsz 256
#define Tn  256
#define In  128
#define Hn  512

// Scratch (allocation-free rule: __device__ globals)
__device__ float g_xs[(size_t)Tn * Bsz * Hn];   // [T][B][H] precomputed input projections + biases
__device__ float g_h[2][Bsz * Hn];              // ping-pong hidden state

// ---------------------------------------------------------------------------
// Zero initial hidden state
// ---------------------------------------------------------------------------
__global__ void init_h_kernel() {
    int i = blockIdx.x * blockDim.x + threadIdx.x;
    if (i < Bsz * Hn) g_h[0][i] = 0.0f;
}

// ---------------------------------------------------------------------------
// xs[t*B+b][h] = sum_i x[b][t][i] * W_ih[h][i] + b_ih[h] + b_hh[h]
// Tiled GEMM: 32x32 tile, 256 threads, 2x2 register blocking, K-chunk 32
// ---------------------------------------------------------------------------
__global__ void xs_kernel(const float* __restrict__ x,
                          const float* __restrict__ W_ih,
                          const float* __restrict__ b_ih,
                          const float* __restrict__ b_hh) {
    __shared__ float As[32][33];
    __shared__ float Ws[32][33];
    int tid = threadIdx.x;
    int tx = tid & 15, ty = tid >> 4;
    int m0 = blockIdx.y * 32;   // m = t*B + b (32 consecutive m share the same t)
    int h0 = blockIdx.x * 32;

    float acc00 = 0.f, acc01 = 0.f, acc10 = 0.f, acc11 = 0.f;

    for (int k0 = 0; k0 < In; k0 += 32) {
        #pragma unroll
        for (int i = 0; i < 4; i++) {
            int idx = tid + i * 256;
            int r = idx >> 5, c = idx & 31;
            int m = m0 + r;
            int t = m >> 8;      // m / B
            int b = m & 255;     // m % B
            As[r][c] = x[((size_t)b * Tn + t) * In + k0 + c];
            Ws[r][c] = W_ih[(h0 + r) * In + k0 + c];
        }
        __syncthreads();
        #pragma unroll
        for (int k = 0; k < 32; k++) {
            float a0 = As[ty * 2][k],     a1 = As[ty * 2 + 1][k];
            float w0 = Ws[tx * 2][k],     w1 = Ws[tx * 2 + 1][k];
            acc00 += a0 * w0; acc01 += a0 * w1;
            acc10 += a1 * w0; acc11 += a1 * w1;
        }
        __syncthreads();
    }

    int h_a = h0 + tx * 2, h_b = h_a + 1;
    float bias_a = b_ih[h_a] + b_hh[h_a];
    float bias_b = b_ih[h_b] + b_hh[h_b];
    size_t m_a = (size_t)(m0 + ty * 2) * Hn;
    size_t m_b = (size_t)(m0 + ty * 2 + 1) * Hn;
    g_xs[m_a + h_a] = acc00 + bias_a;
    g_xs[m_a + h_b] = acc01 + bias_b;
    g_xs[m_b + h_a] = acc10 + bias_a;
    g_xs[m_b + h_b] = acc11 + bias_b;
}

// ---------------------------------------------------------------------------
// One recurrence step: h_new[b][h] = tanh(xs[t][b][h] + sum_k h_prev[b][k]*W_hh[h][k])
// ---------------------------------------------------------------------------
__global__ void step_kernel(const float* __restrict__ W_hh, int t, int src) {
    const float* __restrict__ h_prev = g_h[src];
    float* __restrict__ h_new = g_h[src ^ 1];
    const float* __restrict__ xs_t = g_xs + (size_t)t * Bsz * Hn;

    __shared__ float Hs[32][33];
    __shared__ float Ws[32][33];
    int tid = threadIdx.x;
    int tx = tid & 15, ty = tid >> 4;
    int b0 = blockIdx.y * 32;
    int h0 = blockIdx.x * 32;

    float acc00 = 0.f, acc01 = 0.f, acc10 = 0.f, acc11 = 0.f;

    for (int k0 = 0; k0 < Hn; k0 += 32) {
        #pragma unroll
        for (int i = 0; i < 4; i++) {
            int idx = tid + i * 256;
            int r = idx >> 5, c = idx & 31;
            Hs[r][c] = h_prev[(b0 + r) * Hn + k0 + c];
            Ws[r][c] = W_hh[(h0 + r) * Hn + k0 + c];
        }
        __syncthreads();
        #pragma unroll
        for (int k = 0; k < 32; k++) {
            float hb0 = Hs[ty * 2][k],     hb1 = Hs[ty * 2 + 1][k];
            float w0  = Ws[tx * 2][k],     w1  = Ws[tx * 2 + 1][k];
            acc00 += hb0 * w0; acc01 += hb0 * w1;
            acc10 += hb1 * w0; acc11 += hb1 * w1;
        }
        __syncthreads();
    }

    int b_a = b0 + ty * 2, b_b = b_a + 1;
    int h_a = h0 + tx * 2, h_b = h_a + 1;
    h_new[b_a * Hn + h_a] = tanhf(acc00 + xs_t[b_a * Hn + h_a]);
    h_new[b_a * Hn + h_b] = tanhf(acc01 + xs_t[b_a * Hn + h_b]);
    h_new[b_b * Hn + h_a] = tanhf(acc10 + xs_t[b_b * Hn + h_a]);
    h_new[b_b * Hn + h_b] = tanhf(acc11 + xs_t[b_b * Hn + h_b]);
}

// ---------------------------------------------------------------------------
// out[b] = dot(h_final[b], fc_w) + fc_b[0]
// ---------------------------------------------------------------------------
__global__ void fc_kernel(const float* __restrict__ fc_w,
                          const float* __restrict__ fc_b,
                          float* __restrict__ out, int src) {
    const float* __restrict__ h = g_h[src];
    int b = blockIdx.x;
    float acc = 0.f;
    for (int k = threadIdx.x; k < Hn; k += 128)
        acc += h[b * Hn + k] * fc_w[k];
    __shared__ float s[128];
    s[threadIdx.x] = acc;
    __syncthreads();
    #pragma unroll
    for (int o = 64; o > 0; o >>= 1) {
        if (threadIdx.x < o) s[threadIdx.x] += s[threadIdx.x + o];
        __syncthreads();
    }
    if (threadIdx.x == 0) out[b] = s[0] + fc_b[0];
}

// ---------------------------------------------------------------------------
extern "C" void kernel_launch(void* const* d_in, const int* in_sizes, int n_in,
                              void* d_out, int out_size) {
    const float* x    = (const float*)d_in[0];
    const float* W_ih = (const float*)d_in[1];
    const float* W_hh = (const float*)d_in[2];
    const float* b_ih = (const float*)d_in[3];
    const float* b_hh = (const float*)d_in[4];
    const float* fc_w = (const float*)d_in[5];
    const float* fc_b = (const float*)d_in[6];
    float* out = (float*)d_out;

    init_h_kernel<<<(Bsz * Hn + 255) / 256, 256>>>();

    dim3 gx(Hn / 32, (Tn * Bsz) / 32);   // (16, 2048)
    xs_kernel<<<gx, 256>>>(x, W_ih, b_ih, b_hh);

    dim3 gs(Hn / 32, Bsz / 32);          // (16, 8) = 128 blocks
    int src = 0;
    for (int t = 0; t < Tn; t++) {
        step_kernel<<<gs, 256>>>(W_hh, t, src);
        src ^= 1;
    }

    fc_kernel<<<Bsz, 128>>>(fc_w, fc_b, out, src);
}